// round 16
// baseline (speedup 1.0000x reference)
#include <cuda_runtime.h>
#include <cuda_bf16.h>
#include <math.h>
#include <stdint.h>

#define Bb 16
#define Cc 512
#define Ll 1024
#define C3 1536
#define BN_EPS 1e-5f
#define NB3 3

// ---- scratch (no allocations allowed) ----
__device__ float g_scale[Cc];
__device__ float g_shift[Cc];
__device__ float g_ball[C3];
__device__ float g_rowsum[(size_t)Bb * Ll];               // softmax denominators
__device__ __nv_bfloat16 g_Wall[C3 * Cc];                 // folded QKV weights bf16
__device__ __nv_bfloat16 g_Wpb[Cc * Cc];                  // Wp bf16
__device__ __nv_bfloat16 g_xb[(size_t)Bb * Cc * Ll];      // x bf16
__device__ __nv_bfloat16 g_qkv[(size_t)Bb * C3 * Ll];     // qkv bf16
__device__ __nv_bfloat16 g_P[(size_t)Bb * Ll * Ll];       // unnormalized probs bf16
__device__ __nv_bfloat16 g_h[(size_t)Bb * Cc * Ll];       // attn out bf16

// ---------------- PTX helpers ----------------
__device__ __forceinline__ void cp16(uint32_t saddr, const void* gaddr) {
    asm volatile("cp.async.cg.shared.global [%0], [%1], 16;\n" :: "r"(saddr), "l"(gaddr));
}
// .noinc: the barrier's init count already budgets one arrival per thread.
__device__ __forceinline__ void cp_mbar_arrive(uint32_t mbar) {
    asm volatile("cp.async.mbarrier.arrive.noinc.shared::cta.b64 [%0];\n" :: "r"(mbar) : "memory");
}
__device__ __forceinline__ void mbar_init(uint32_t mbar, uint32_t cnt) {
    asm volatile("mbarrier.init.shared.b64 [%0], %1;" :: "r"(mbar), "r"(cnt) : "memory");
}
__device__ __forceinline__ void mbar_arrive(uint32_t mbar) {
    asm volatile("mbarrier.arrive.shared.b64 _, [%0];" :: "r"(mbar) : "memory");
}
__device__ __forceinline__ void mbar_wait(uint32_t mbar, uint32_t parity) {
    asm volatile(
        "{\n\t.reg .pred P;\n"
        "WL_%=: mbarrier.try_wait.parity.acquire.cta.shared::cta.b64 P, [%0], %1, 0x989680;\n"
        "@P bra.uni WD_%=;\n"
        "bra.uni WL_%=;\n"
        "WD_%=:\n\t}"
        :: "r"(mbar), "r"(parity) : "memory");
}
__device__ __forceinline__ void ldsm_x4(uint32_t* r, uint32_t a) {
    asm volatile("ldmatrix.sync.aligned.m8n8.x4.shared.b16 {%0,%1,%2,%3}, [%4];"
                 : "=r"(r[0]), "=r"(r[1]), "=r"(r[2]), "=r"(r[3]) : "r"(a));
}
__device__ __forceinline__ void ldsm_x4t(uint32_t* r, uint32_t a) {
    asm volatile("ldmatrix.sync.aligned.m8n8.x4.trans.shared.b16 {%0,%1,%2,%3}, [%4];"
                 : "=r"(r[0]), "=r"(r[1]), "=r"(r[2]), "=r"(r[3]) : "r"(a));
}
__device__ __forceinline__ void ldsm_x2(uint32_t* r, uint32_t a) {
    asm volatile("ldmatrix.sync.aligned.m8n8.x2.shared.b16 {%0,%1}, [%2];"
                 : "=r"(r[0]), "=r"(r[1]) : "r"(a));
}
__device__ __forceinline__ void ldsm_x2t(uint32_t* r, uint32_t a) {
    asm volatile("ldmatrix.sync.aligned.m8n8.x2.trans.shared.b16 {%0,%1}, [%2];"
                 : "=r"(r[0]), "=r"(r[1]) : "r"(a));
}
__device__ __forceinline__ void mma_bf16(float* c, const uint32_t* a, const uint32_t* b) {
    asm volatile(
        "mma.sync.aligned.m16n8k16.row.col.f32.bf16.bf16.f32 "
        "{%0,%1,%2,%3}, {%4,%5,%6,%7}, {%8,%9}, {%0,%1,%2,%3};"
        : "+f"(c[0]), "+f"(c[1]), "+f"(c[2]), "+f"(c[3])
        : "r"(a[0]), "r"(a[1]), "r"(a[2]), "r"(a[3]), "r"(b[0]), "r"(b[1]));
}

// ============================================================
// BatchNorm stats + fused x -> bf16 conversion
// ============================================================
__global__ __launch_bounds__(256) void bn_stats_kernel(
    const float* __restrict__ x, const float* __restrict__ gamma,
    const float* __restrict__ beta)
{
    int c = blockIdx.x;
    int tid = threadIdx.x;
    float s = 0.f, s2 = 0.f;
    for (int i = tid; i < (Bb * Ll) / 4; i += 256) {
        int b = i >> 8, l4 = i & 255;
        size_t off = (size_t)b * Cc * Ll + (size_t)c * Ll + l4 * 4;
        float4 v = *(const float4*)(x + off);
        s += v.x + v.y + v.z + v.w;
        s2 += v.x * v.x + v.y * v.y + v.z * v.z + v.w * v.w;
        __nv_bfloat162 h0 = { __float2bfloat16(v.x), __float2bfloat16(v.y) };
        __nv_bfloat162 h1 = { __float2bfloat16(v.z), __float2bfloat16(v.w) };
        *(__nv_bfloat162*)(g_xb + off) = h0;
        *(__nv_bfloat162*)(g_xb + off + 2) = h1;
    }
    __shared__ float sh1[256], sh2[256];
    sh1[tid] = s; sh2[tid] = s2; __syncthreads();
    for (int o = 128; o > 0; o >>= 1) {
        if (tid < o) { sh1[tid] += sh1[tid + o]; sh2[tid] += sh2[tid + o]; }
        __syncthreads();
    }
    if (tid == 0) {
        const float inv_n = 1.f / (float)(Bb * Ll);
        float mean = sh1[0] * inv_n;
        float var = sh2[0] * inv_n - mean * mean;
        float sc = gamma[c] * rsqrtf(var + BN_EPS);
        g_scale[c] = sc;
        g_shift[c] = beta[c] - mean * sc;
    }
}

// ============================================================
// Fold BN into stacked QKV weights (bf16) + biases
// ============================================================
__global__ __launch_bounds__(256) void fold_kernel(
    const float* __restrict__ Wq, const float* __restrict__ bq,
    const float* __restrict__ Wk, const float* __restrict__ bk,
    const float* __restrict__ Wv, const float* __restrict__ bv)
{
    int o = blockIdx.x;
    int r = o & (Cc - 1);
    const float* W; const float* bb;
    if (o < Cc)          { W = Wq; bb = bq; }
    else if (o < 2 * Cc) { W = Wk; bb = bk; }
    else                 { W = Wv; bb = bv; }
    int tid = threadIdx.x;
    float acc = 0.f;
    for (int c = tid; c < Cc; c += 256) {
        float w = W[r * Cc + c];
        g_Wall[o * Cc + c] = __float2bfloat16(w * g_scale[c]);
        acc += w * g_shift[c];
    }
    __shared__ float sh[256];
    sh[tid] = acc; __syncthreads();
    for (int off = 128; off > 0; off >>= 1) {
        if (tid < off) sh[tid] += sh[tid + off];
        __syncthreads();
    }
    if (tid == 0) g_ball[o] = bb[r] + sh[0];
}

// fp32 -> bf16 (for Wp)
__global__ __launch_bounds__(256) void conv_kernel(
    const float* __restrict__ in, __nv_bfloat16* __restrict__ outp)
{
    size_t i = ((size_t)blockIdx.x * 256 + threadIdx.x) * 4;
    float4 v = *(const float4*)(in + i);
    *(__nv_bfloat162*)(outp + i)     = { __float2bfloat16(v.x), __float2bfloat16(v.y) };
    *(__nv_bfloat162*)(outp + i + 2) = { __float2bfloat16(v.z), __float2bfloat16(v.w) };
}

// ============================================================
// bf16 TC GEMM: C[m][n] = op( sum_k A(k,m)*B(k,n) )
// Tile 128x128, 8 warps (64x32 warp tiles), k-stage 64 (4 ks halves).
// NB3=3 smem buffers, mbarrier producer/consumer pipeline
// (full: 256 cp.async.noinc arrivals; empty: 8 warp arrivals),
// no __syncthreads in mainloop, fragment double-buffering.
// A_KC: A gmem [M][K] k-contig -> smem [m][72e/144B]; else [K][M] -> [k][136e/272B]
// EPI: 1 = +bias[row] -> bf16 (QKV)
//      2 = exp(v*scale) -> bf16 P + rowsum atomics (scores)
//      3 = +bias[row]+resid -> fp32 (proj)
//      4 = v / rowsum[col] -> bf16 (AV)
// ============================================================
template<bool A_KC, bool B_KC, int EPI>
__global__ __launch_bounds__(256, 2) void gemm_bf(
    const __nv_bfloat16* __restrict__ Ag, const __nv_bfloat16* __restrict__ Bg,
    void* __restrict__ Cg, int Kdim, int ldA, int ldB, int ldC,
    size_t sA, size_t sB, size_t sC,
    const float* __restrict__ bias, const float* __restrict__ resid,
    float* __restrict__ rowsum, float scale)
{
    constexpr int ABYTES = A_KC ? 128 * 144 : 64 * 272;
    constexpr int BBYTES = B_KC ? 128 * 144 : 64 * 272;
    extern __shared__ __align__(16) unsigned char smem_raw[];
    const uint32_t smem0 = (uint32_t)__cvta_generic_to_shared(smem_raw);
    const uint32_t FB = smem0, EB = smem0 + 24;      // 3 x 8B each
    const uint32_t BUF = smem0 + 640;

    const int tid = threadIdx.x;
    const int lane = tid & 31, wid = tid >> 5;
    const int lr = lane >> 2, lc = lane & 3;
    const int wm = (wid >> 2) * 64;
    const int wn = (wid & 3) * 32;
    const int m0 = blockIdx.y * 128, n0 = blockIdx.x * 128;
    const int bz = blockIdx.z;

    if (tid == 0) {
#pragma unroll
        for (int i = 0; i < NB3; i++) {
            mbar_init(FB + i * 8, 256);
            mbar_init(EB + i * 8, 8);
        }
    }
    __syncthreads();

    const __nv_bfloat16* Ap = Ag + sA * bz;
    const __nv_bfloat16* Bp = Bg + sB * bz;

    // ---- cp.async loaders: 4 x 16B per thread per operand per stage (k=64) ----
    const __nv_bfloat16* ag; uint32_t aSm; size_t aStep;
    if (A_KC) {              // 128 rows x 128B data (144B padded): 2 threads/row
        int r = tid >> 1, h = tid & 1;
        ag = Ap + (size_t)(m0 + r) * ldA + h * 32;
        aSm = r * 144 + h * 64; aStep = 64;
    } else {                 // 64 k-rows x 256B data (272B padded): 4 threads/row
        int r = tid >> 2, q = tid & 3;
        ag = Ap + (size_t)r * ldA + m0 + q * 32;
        aSm = r * 272 + q * 64; aStep = (size_t)64 * ldA;
    }
    const __nv_bfloat16* bg; uint32_t bSm; size_t bStep;
    if (B_KC) {
        int r = tid >> 1, h = tid & 1;
        bg = Bp + (size_t)(n0 + r) * ldB + h * 32;
        bSm = r * 144 + h * 64; bStep = 64;
    } else {
        int r = tid >> 2, q = tid & 3;
        bg = Bp + (size_t)r * ldB + n0 + q * 32;
        bSm = r * 272 + q * 64; bStep = (size_t)64 * ldB;
    }

    // ---- ldmatrix base offsets (bytes) ----
    uint32_t abase, bbase;
    if (A_KC)
        abase = (uint32_t)((wm + (lane & 15)) * 72 + (lane >> 4) * 8) * 2;
    else
        abase = (uint32_t)((((lane & 7) + ((lane >> 4) << 3)) * 136) + wm + ((lane >> 3) & 1) * 8) * 2;
    if (B_KC)
        bbase = (uint32_t)((wn + (lane & 7)) * 72 + ((lane >> 3) & 1) * 8) * 2;
    else
        bbase = (uint32_t)(((lane & 15)) * 136 + wn) * 2;

    float acc[4][4][4];
#pragma unroll
    for (int i = 0; i < 4; i++)
#pragma unroll
        for (int j = 0; j < 4; j++)
#pragma unroll
            for (int q = 0; q < 4; q++) acc[i][j][q] = 0.f;

    const int nStages = Kdim / 64;

    auto loadStage = [&](int s, int buf) {
        const uint32_t aB = BUF + buf * ABYTES;
        const uint32_t bB = BUF + NB3 * ABYTES + buf * BBYTES;
        const __nv_bfloat16* an = ag + (size_t)s * aStep;
        const __nv_bfloat16* bn = bg + (size_t)s * bStep;
#pragma unroll
        for (int i = 0; i < 4; i++) {
            cp16(aB + aSm + i * 16, an + i * 8);
            cp16(bB + bSm + i * 16, bn + i * 8);
        }
        cp_mbar_arrive(FB + buf * 8);
    };
    auto ldsmAB = [&](int buf, int ks, uint32_t af[4][4], uint32_t bf[4][2]) {
        const uint32_t aB = BUF + buf * ABYTES;
        const uint32_t bB = BUF + NB3 * ABYTES + buf * BBYTES;
#pragma unroll
        for (int mt = 0; mt < 4; mt++) {
            uint32_t addr = aB + abase +
                (A_KC ? (uint32_t)(mt * 16 * 72 + ks * 16) * 2
                      : (uint32_t)(mt * 16 + ks * 16 * 136) * 2);
            if (A_KC) ldsm_x4(af[mt], addr); else ldsm_x4t(af[mt], addr);
        }
#pragma unroll
        for (int nt = 0; nt < 4; nt++) {
            uint32_t addr = bB + bbase +
                (B_KC ? (uint32_t)(nt * 8 * 72 + ks * 16) * 2
                      : (uint32_t)(nt * 8 + ks * 16 * 136) * 2);
            if (B_KC) ldsm_x2(bf[nt], addr); else ldsm_x2t(bf[nt], addr);
        }
    };

    // prologue: stages 0,1 in flight (buffers 0,1); frags(0, ks0) resident
    loadStage(0, 0); loadStage(1, 1);

    uint32_t af0[4][4], bf0[4][2], af1[4][4], bf1[4][2];
    mbar_wait(FB + 0, 0);
    ldsmAB(0, 0, af0, bf0);

#define MMA_TILE(AF, BF) \
    _Pragma("unroll") \
    for (int mt = 0; mt < 4; mt++) \
        _Pragma("unroll") \
        for (int nt = 0; nt < 4; nt++) \
            mma_bf16(acc[mt][nt], AF[mt], BF[nt]);

    for (int s = 0; s < nStages; s++) {
        const int buf = s % NB3;

        // ks 0 -> 1 -> 2 with fragment double-buffer
        ldsmAB(buf, 1, af1, bf1);
        MMA_TILE(af0, bf0);
        ldsmAB(buf, 2, af0, bf0);
        MMA_TILE(af1, bf1);

        // producer: issue stage s+2
        const int t = s + 2;
        if (t < nStages) {
            const int tb = t % NB3;
            if (t >= NB3) mbar_wait(EB + tb * 8, (uint32_t)(((t - NB3) / NB3) & 1));
            loadStage(t, tb);
        }

        ldsmAB(buf, 3, af1, bf1);
        MMA_TILE(af0, bf0);

        // consumer: fetch frags(s+1, ks0)
        if (s + 1 < nStages) {
            const int nb = (s + 1) % NB3;
            mbar_wait(FB + nb * 8, (uint32_t)(((s + 1) / NB3) & 1));
            ldsmAB(nb, 0, af0, bf0);
        }
        MMA_TILE(af1, bf1);

        if (lane == 0) mbar_arrive(EB + buf * 8);
    }
#undef MMA_TILE
    __syncthreads();

    // ---- epilogue ----
    if (EPI == 2) {
        float* rsum = (float*)(smem_raw + 128);   // clear of mbarrier words
        if (tid < 128) rsum[tid] = 0.f;
        __syncthreads();
        __nv_bfloat16* Cb = (__nv_bfloat16*)Cg + sC * bz;
#pragma unroll
        for (int mt = 0; mt < 4; mt++) {
            int row = m0 + wm + mt * 16 + lr;
            float p0 = 0.f, p1 = 0.f;
#pragma unroll
            for (int nt = 0; nt < 4; nt++) {
                int col = n0 + wn + nt * 8 + 2 * lc;
                float e0 = __expf(acc[mt][nt][0] * scale);
                float e1 = __expf(acc[mt][nt][1] * scale);
                float e2 = __expf(acc[mt][nt][2] * scale);
                float e3 = __expf(acc[mt][nt][3] * scale);
                p0 += e0 + e1; p1 += e2 + e3;
                __nv_bfloat162 q0 = { __float2bfloat16(e0), __float2bfloat16(e1) };
                __nv_bfloat162 q1 = { __float2bfloat16(e2), __float2bfloat16(e3) };
                *(__nv_bfloat162*)&Cb[(size_t)row * ldC + col] = q0;
                *(__nv_bfloat162*)&Cb[(size_t)(row + 8) * ldC + col] = q1;
            }
            atomicAdd(&rsum[wm + mt * 16 + lr], p0);
            atomicAdd(&rsum[wm + mt * 16 + lr + 8], p1);
        }
        __syncthreads();
        if (tid < 128)
            atomicAdd(&rowsum[(size_t)bz * Ll + m0 + tid], rsum[tid]);
        return;
    }

#pragma unroll
    for (int mt = 0; mt < 4; mt++) {
#pragma unroll
        for (int nt = 0; nt < 4; nt++) {
            int row = m0 + wm + mt * 16 + lr;
            int col = n0 + wn + nt * 8 + 2 * lc;
            float v0 = acc[mt][nt][0], v1 = acc[mt][nt][1];
            float v2 = acc[mt][nt][2], v3 = acc[mt][nt][3];
            if (EPI == 1) {
                float b0 = bias[row], b1 = bias[row + 8];
                v0 += b0; v1 += b0; v2 += b1; v3 += b1;
                __nv_bfloat16* Cb = (__nv_bfloat16*)Cg + sC * bz;
                __nv_bfloat162 p0 = { __float2bfloat16(v0), __float2bfloat16(v1) };
                __nv_bfloat162 p1 = { __float2bfloat16(v2), __float2bfloat16(v3) };
                *(__nv_bfloat162*)&Cb[(size_t)row * ldC + col] = p0;
                *(__nv_bfloat162*)&Cb[(size_t)(row + 8) * ldC + col] = p1;
            } else if (EPI == 4) {
                const float* rs = rowsum + (size_t)bz * Ll;
                float2 rv = *(const float2*)&rs[col];
                float i0 = __fdividef(1.f, rv.x), i1 = __fdividef(1.f, rv.y);
                v0 *= i0; v1 *= i1; v2 *= i0; v3 *= i1;
                __nv_bfloat16* Cb = (__nv_bfloat16*)Cg + sC * bz;
                __nv_bfloat162 p0 = { __float2bfloat16(v0), __float2bfloat16(v1) };
                __nv_bfloat162 p1 = { __float2bfloat16(v2), __float2bfloat16(v3) };
                *(__nv_bfloat162*)&Cb[(size_t)row * ldC + col] = p0;
                *(__nv_bfloat162*)&Cb[(size_t)(row + 8) * ldC + col] = p1;
            } else { // EPI == 3
                float* Cf = (float*)Cg + sC * bz;
                float b0 = bias[row], b1 = bias[row + 8];
                const float* rp = resid + sC * bz;
                float2 r0 = *(const float2*)&rp[(size_t)row * ldC + col];
                float2 r1 = *(const float2*)&rp[(size_t)(row + 8) * ldC + col];
                v0 += b0 + r0.x; v1 += b0 + r0.y;
                v2 += b1 + r1.x; v3 += b1 + r1.y;
                *(float2*)&Cf[(size_t)row * ldC + col] = make_float2(v0, v1);
                *(float2*)&Cf[(size_t)(row + 8) * ldC + col] = make_float2(v2, v3);
            }
        }
    }
}

// ============================================================
extern "C" void kernel_launch(void* const* d_in, const int* in_sizes, int n_in,
                              void* d_out, int out_size)
{
    const float* x     = (const float*)d_in[0];
    const float* gamma = (const float*)d_in[1];
    const float* beta  = (const float*)d_in[2];
    const float* Wq    = (const float*)d_in[3];
    const float* bq    = (const float*)d_in[4];
    const float* Wk    = (const float*)d_in[5];
    const float* bk    = (const float*)d_in[6];
    const float* Wv    = (const float*)d_in[7];
    const float* bv    = (const float*)d_in[8];
    const float* Wp    = (const float*)d_in[9];
    const float* bp    = (const float*)d_in[10];
    float* out = (float*)d_out;

    __nv_bfloat16 *Wall, *Wpb, *xb, *qkv, *P, *h;
    float *ball, *rowsum;
    cudaGetSymbolAddress((void**)&Wall, g_Wall);
    cudaGetSymbolAddress((void**)&Wpb,  g_Wpb);
    cudaGetSymbolAddress((void**)&xb,   g_xb);
    cudaGetSymbolAddress((void**)&qkv,  g_qkv);
    cudaGetSymbolAddress((void**)&P,    g_P);
    cudaGetSymbolAddress((void**)&h,    g_h);
    cudaGetSymbolAddress((void**)&ball, g_ball);
    cudaGetSymbolAddress((void**)&rowsum, g_rowsum);

    const int SM_TF = 640 + NB3 * (128 * 144 + 64 * 272);   // 108160
    const int SM_FF = 640 + NB3 * (64 * 272 + 64 * 272);    // 105088
    const int SM_TT = 640 + NB3 * (128 * 144 + 128 * 144);  // 111232
    cudaFuncSetAttribute(gemm_bf<true,  false, 1>, cudaFuncAttributeMaxDynamicSharedMemorySize, SM_TF);
    cudaFuncSetAttribute(gemm_bf<false, false, 2>, cudaFuncAttributeMaxDynamicSharedMemorySize, SM_FF);
    cudaFuncSetAttribute(gemm_bf<true,  true,  4>, cudaFuncAttributeMaxDynamicSharedMemorySize, SM_TT);
    cudaFuncSetAttribute(gemm_bf<true,  false, 3>, cudaFuncAttributeMaxDynamicSharedMemorySize, SM_TF);

    bn_stats_kernel<<<Cc, 256>>>(x, gamma, beta);
    fold_kernel<<<C3, 256>>>(Wq, bq, Wk, bk, Wv, bv);
    conv_kernel<<<(Cc * Cc) / 1024, 256>>>(Wp, Wpb);
    cudaMemsetAsync(rowsum, 0, (size_t)Bb * Ll * sizeof(float), 0);

    // QKV: qkv[o][l] = sum_c Wall[o][c] xb[c][l] + ball[o]   -> bf16
    gemm_bf<true, false, 1><<<dim3(Ll / 128, C3 / 128, Bb), 256, SM_TF>>>(
        Wall, xb, qkv, Cc, Cc, Ll, Ll,
        0, (size_t)Cc * Ll, (size_t)C3 * Ll, ball, nullptr, nullptr, 0.f);

    // scores+exp: P[i][j] = exp(scale * sum_c q[c][i] k[c][j]), rowsum accum
    gemm_bf<false, false, 2><<<dim3(Ll / 128, Ll / 128, Bb), 256, SM_FF>>>(
        qkv, qkv + (size_t)Cc * Ll, P, Cc, Ll, Ll, Ll,
        (size_t)C3 * Ll, (size_t)C3 * Ll, (size_t)Ll * Ll,
        nullptr, nullptr, rowsum, rsqrtf((float)Cc));

    // AV + normalize: h[c][i] = (sum_j V[c][j] P[i][j]) / rowsum[i]  -> bf16
    gemm_bf<true, true, 4><<<dim3(Ll / 128, Cc / 128, Bb), 256, SM_TT>>>(
        qkv + (size_t)2 * Cc * Ll, P, h, Ll, Ll, Ll, Ll,
        (size_t)C3 * Ll, (size_t)Ll * Ll, (size_t)Cc * Ll,
        nullptr, nullptr, rowsum, 0.f);

    // proj: out[o][l] = x[o][l] + bp[o] + sum_c Wp[o][c] h[c][l]  -> fp32
    gemm_bf<true, false, 3><<<dim3(Ll / 128, Cc / 128, Bb), 256, SM_TF>>>(
        Wpb, h, out, Cc, Cc, Ll, Ll,
        0, (size_t)Cc * Ll, (size_t)Cc * Ll, bp, x, nullptr, 0.f);
}

// round 17
// speedup vs baseline: 1.1883x; 1.1883x over previous
#include <cuda_runtime.h>
#include <cuda_bf16.h>
#include <math.h>
#include <stdint.h>

#define Bb 16
#define Cc 512
#define Ll 1024
#define C3 1536
#define BN_EPS 1e-5f
#define NBUF 5

// ---- scratch (no allocations allowed) ----
__device__ float g_scale[Cc];
__device__ float g_shift[Cc];
__device__ float g_ball[C3];
__device__ float g_rowsum[(size_t)Bb * Ll];               // softmax denominators
__device__ __nv_bfloat16 g_Wall[C3 * Cc];                 // folded QKV weights bf16
__device__ __nv_bfloat16 g_Wpb[Cc * Cc];                  // Wp bf16
__device__ __nv_bfloat16 g_xb[(size_t)Bb * Cc * Ll];      // x bf16
__device__ __nv_bfloat16 g_qkv[(size_t)Bb * C3 * Ll];     // qkv bf16
__device__ __nv_bfloat16 g_P[(size_t)Bb * Ll * Ll];       // unnormalized probs bf16
__device__ __nv_bfloat16 g_h[(size_t)Bb * Cc * Ll];       // attn out bf16

// ---------------- PTX helpers ----------------
__device__ __forceinline__ void cp16(uint32_t saddr, const void* gaddr) {
    asm volatile("cp.async.cg.shared.global [%0], [%1], 16;\n" :: "r"(saddr), "l"(gaddr));
}
// .noinc: the barrier's init count already budgets one arrival per thread.
__device__ __forceinline__ void cp_mbar_arrive(uint32_t mbar) {
    asm volatile("cp.async.mbarrier.arrive.noinc.shared::cta.b64 [%0];\n" :: "r"(mbar) : "memory");
}
__device__ __forceinline__ void mbar_init(uint32_t mbar, uint32_t cnt) {
    asm volatile("mbarrier.init.shared.b64 [%0], %1;" :: "r"(mbar), "r"(cnt) : "memory");
}
__device__ __forceinline__ void mbar_arrive(uint32_t mbar) {
    asm volatile("mbarrier.arrive.shared.b64 _, [%0];" :: "r"(mbar) : "memory");
}
__device__ __forceinline__ void mbar_wait(uint32_t mbar, uint32_t parity) {
    asm volatile(
        "{\n\t.reg .pred P;\n"
        "WL_%=: mbarrier.try_wait.parity.acquire.cta.shared::cta.b64 P, [%0], %1, 0x989680;\n"
        "@P bra.uni WD_%=;\n"
        "bra.uni WL_%=;\n"
        "WD_%=:\n\t}"
        :: "r"(mbar), "r"(parity) : "memory");
}
__device__ __forceinline__ void ldsm_x4(uint32_t* r, uint32_t a) {
    asm volatile("ldmatrix.sync.aligned.m8n8.x4.shared.b16 {%0,%1,%2,%3}, [%4];"
                 : "=r"(r[0]), "=r"(r[1]), "=r"(r[2]), "=r"(r[3]) : "r"(a));
}
__device__ __forceinline__ void ldsm_x4t(uint32_t* r, uint32_t a) {
    asm volatile("ldmatrix.sync.aligned.m8n8.x4.trans.shared.b16 {%0,%1,%2,%3}, [%4];"
                 : "=r"(r[0]), "=r"(r[1]), "=r"(r[2]), "=r"(r[3]) : "r"(a));
}
__device__ __forceinline__ void ldsm_x2(uint32_t* r, uint32_t a) {
    asm volatile("ldmatrix.sync.aligned.m8n8.x2.shared.b16 {%0,%1}, [%2];"
                 : "=r"(r[0]), "=r"(r[1]) : "r"(a));
}
__device__ __forceinline__ void ldsm_x2t(uint32_t* r, uint32_t a) {
    asm volatile("ldmatrix.sync.aligned.m8n8.x2.trans.shared.b16 {%0,%1}, [%2];"
                 : "=r"(r[0]), "=r"(r[1]) : "r"(a));
}
__device__ __forceinline__ void mma_bf16(float* c, const uint32_t* a, const uint32_t* b) {
    asm volatile(
        "mma.sync.aligned.m16n8k16.row.col.f32.bf16.bf16.f32 "
        "{%0,%1,%2,%3}, {%4,%5,%6,%7}, {%8,%9}, {%0,%1,%2,%3};"
        : "+f"(c[0]), "+f"(c[1]), "+f"(c[2]), "+f"(c[3])
        : "r"(a[0]), "r"(a[1]), "r"(a[2]), "r"(a[3]), "r"(b[0]), "r"(b[1]));
}

// ============================================================
// BatchNorm stats + fused x -> bf16 conversion
// ============================================================
__global__ __launch_bounds__(256) void bn_stats_kernel(
    const float* __restrict__ x, const float* __restrict__ gamma,
    const float* __restrict__ beta)
{
    int c = blockIdx.x;
    int tid = threadIdx.x;
    float s = 0.f, s2 = 0.f;
    for (int i = tid; i < (Bb * Ll) / 4; i += 256) {
        int b = i >> 8, l4 = i & 255;
        size_t off = (size_t)b * Cc * Ll + (size_t)c * Ll + l4 * 4;
        float4 v = *(const float4*)(x + off);
        s += v.x + v.y + v.z + v.w;
        s2 += v.x * v.x + v.y * v.y + v.z * v.z + v.w * v.w;
        __nv_bfloat162 h0 = { __float2bfloat16(v.x), __float2bfloat16(v.y) };
        __nv_bfloat162 h1 = { __float2bfloat16(v.z), __float2bfloat16(v.w) };
        *(__nv_bfloat162*)(g_xb + off) = h0;
        *(__nv_bfloat162*)(g_xb + off + 2) = h1;
    }
    __shared__ float sh1[256], sh2[256];
    sh1[tid] = s; sh2[tid] = s2; __syncthreads();
    for (int o = 128; o > 0; o >>= 1) {
        if (tid < o) { sh1[tid] += sh1[tid + o]; sh2[tid] += sh2[tid + o]; }
        __syncthreads();
    }
    if (tid == 0) {
        const float inv_n = 1.f / (float)(Bb * Ll);
        float mean = sh1[0] * inv_n;
        float var = sh2[0] * inv_n - mean * mean;
        float sc = gamma[c] * rsqrtf(var + BN_EPS);
        g_scale[c] = sc;
        g_shift[c] = beta[c] - mean * sc;
    }
}

// ============================================================
// Fold BN into stacked QKV weights (bf16) + biases.
// Blocks >= C3 convert Wp fp32 -> bf16 (merged to save a launch).
// ============================================================
__global__ __launch_bounds__(256) void fold_kernel(
    const float* __restrict__ Wq, const float* __restrict__ bq,
    const float* __restrict__ Wk, const float* __restrict__ bk,
    const float* __restrict__ Wv, const float* __restrict__ bv,
    const float* __restrict__ Wp)
{
    int o = blockIdx.x;
    int tid = threadIdx.x;
    if (o >= C3) {
        // Wp conversion: 256 blocks x 1024 elems
        size_t i = ((size_t)(o - C3) * 256 + tid) * 4;
        float4 v = *(const float4*)(Wp + i);
        *(__nv_bfloat162*)(g_Wpb + i)     = { __float2bfloat16(v.x), __float2bfloat16(v.y) };
        *(__nv_bfloat162*)(g_Wpb + i + 2) = { __float2bfloat16(v.z), __float2bfloat16(v.w) };
        return;
    }
    int r = o & (Cc - 1);
    const float* W; const float* bb;
    if (o < Cc)          { W = Wq; bb = bq; }
    else if (o < 2 * Cc) { W = Wk; bb = bk; }
    else                 { W = Wv; bb = bv; }
    float acc = 0.f;
    for (int c = tid; c < Cc; c += 256) {
        float w = W[r * Cc + c];
        g_Wall[o * Cc + c] = __float2bfloat16(w * g_scale[c]);
        acc += w * g_shift[c];
    }
    __shared__ float sh[256];
    sh[tid] = acc; __syncthreads();
    for (int off = 128; off > 0; off >>= 1) {
        if (tid < off) sh[tid] += sh[tid + off];
        __syncthreads();
    }
    if (tid == 0) g_ball[o] = bb[r] + sh[0];
}

// ============================================================
// bf16 TC GEMM: C[m][n] = op( sum_k A(k,m)*B(k,n) )
// Tile 128x128, 8 warps (64x32 warp tiles), k-stage 32.
// NBUF=5 smem buffers, mbarrier producer/consumer pipeline
// (full: 256 cp.async.noinc arrivals; empty: 8 warp arrivals),
// NO __syncthreads in the mainloop. Fragment double-buffering.
// EPI: 1 = +bias[row] -> bf16 (QKV)
//      2 = exp(v*scale) -> bf16 P + rowsum atomics (scores)
//      3 = +bias[row]+resid -> fp32 (proj)
//      4 = v / rowsum[col] -> bf16 (AV)
// ============================================================
template<bool A_KC, bool B_KC, int EPI>
__global__ __launch_bounds__(256, 2) void gemm_bf(
    const __nv_bfloat16* __restrict__ Ag, const __nv_bfloat16* __restrict__ Bg,
    void* __restrict__ Cg, int Kdim, int ldA, int ldB, int ldC,
    size_t sA, size_t sB, size_t sC,
    const float* __restrict__ bias, const float* __restrict__ resid,
    float* __restrict__ rowsum, float scale)
{
    constexpr int ABYTES = A_KC ? 128 * 80 : 32 * 272;
    constexpr int BBYTES = B_KC ? 128 * 80 : 32 * 272;
    extern __shared__ __align__(16) unsigned char smem_raw[];
    const uint32_t smem0 = (uint32_t)__cvta_generic_to_shared(smem_raw);
    const uint32_t FB = smem0, EB = smem0 + 40;
    const uint32_t BUF = smem0 + 640;

    const int tid = threadIdx.x;
    const int lane = tid & 31, wid = tid >> 5;
    const int lr = lane >> 2, lc = lane & 3;
    const int wm = (wid >> 2) * 64;
    const int wn = (wid & 3) * 32;
    const int m0 = blockIdx.y * 128, n0 = blockIdx.x * 128;
    const int bz = blockIdx.z;

    if (tid == 0) {
#pragma unroll
        for (int i = 0; i < NBUF; i++) {
            mbar_init(FB + i * 8, 256);
            mbar_init(EB + i * 8, 8);
        }
    }
    __syncthreads();

    const __nv_bfloat16* Ap = Ag + sA * bz;
    const __nv_bfloat16* Bp = Bg + sB * bz;

    // ---- cp.async loaders: 2 x 16B per thread per operand per stage (k=32) ----
    const __nv_bfloat16* ag; uint32_t aSm; size_t aStep;
    if (A_KC) {
        int r = tid >> 1, c = (tid & 1) * 2;
        ag = Ap + (size_t)(m0 + r) * ldA + c * 8;
        aSm = r * 80 + c * 16; aStep = 32;
    } else {
        int r = tid >> 3, c = (tid & 7) * 2;
        ag = Ap + (size_t)r * ldA + m0 + c * 8;
        aSm = r * 272 + c * 16; aStep = (size_t)32 * ldA;
    }
    const __nv_bfloat16* bg; uint32_t bSm; size_t bStep;
    if (B_KC) {
        int r = tid >> 1, c = (tid & 1) * 2;
        bg = Bp + (size_t)(n0 + r) * ldB + c * 8;
        bSm = r * 80 + c * 16; bStep = 32;
    } else {
        int r = tid >> 3, c = (tid & 7) * 2;
        bg = Bp + (size_t)r * ldB + n0 + c * 8;
        bSm = r * 272 + c * 16; bStep = (size_t)32 * ldB;
    }

    // ---- ldmatrix base offsets (bytes) ----
    uint32_t abase, bbase;
    if (A_KC)
        abase = (uint32_t)((wm + (lane & 15)) * 40 + (lane >> 4) * 8) * 2;
    else
        abase = (uint32_t)((((lane & 7) + ((lane >> 4) << 3)) * 136) + wm + ((lane >> 3) & 1) * 8) * 2;
    if (B_KC)
        bbase = (uint32_t)((wn + (lane & 7)) * 40 + ((lane >> 3) & 1) * 8) * 2;
    else
        bbase = (uint32_t)(((lane & 15)) * 136 + wn) * 2;

    float acc[4][4][4];
#pragma unroll
    for (int i = 0; i < 4; i++)
#pragma unroll
        for (int j = 0; j < 4; j++)
#pragma unroll
            for (int q = 0; q < 4; q++) acc[i][j][q] = 0.f;

    const int nStages = Kdim / 32;

    auto loadStage = [&](int s, int buf) {
        const uint32_t aB = BUF + buf * ABYTES;
        const uint32_t bB = BUF + NBUF * ABYTES + buf * BBYTES;
        const __nv_bfloat16* an = ag + (size_t)s * aStep;
        const __nv_bfloat16* bn = bg + (size_t)s * bStep;
        cp16(aB + aSm, an);      cp16(aB + aSm + 16, an + 8);
        cp16(bB + bSm, bn);      cp16(bB + bSm + 16, bn + 8);
        cp_mbar_arrive(FB + buf * 8);
    };
    auto ldsmAB = [&](int buf, int ks, uint32_t af[4][4], uint32_t bf[4][2]) {
        const uint32_t aB = BUF + buf * ABYTES;
        const uint32_t bB = BUF + NBUF * ABYTES + buf * BBYTES;
#pragma unroll
        for (int mt = 0; mt < 4; mt++) {
            uint32_t addr = aB + abase +
                (A_KC ? (uint32_t)(mt * 16 * 40 + ks * 16) * 2
                      : (uint32_t)(mt * 16 + ks * 16 * 136) * 2);
            if (A_KC) ldsm_x4(af[mt], addr); else ldsm_x4t(af[mt], addr);
        }
#pragma unroll
        for (int nt = 0; nt < 4; nt++) {
            uint32_t addr = bB + bbase +
                (B_KC ? (uint32_t)(nt * 8 * 40 + ks * 16) * 2
                      : (uint32_t)(nt * 8 + ks * 16 * 136) * 2);
            if (B_KC) ldsm_x2(bf[nt], addr); else ldsm_x2t(bf[nt], addr);
        }
    };

    // prologue: stages 0..2 in flight (buffers 0..2), frags(0,0) resident
    loadStage(0, 0); loadStage(1, 1); loadStage(2, 2);

    uint32_t af0[4][4], bf0[4][2], af1[4][4], bf1[4][2];
    mbar_wait(FB + 0, 0);
    ldsmAB(0, 0, af0, bf0);

    for (int s = 0; s < nStages; s++) {
        const int buf = s % NBUF;

        // ---- ks = 0: prefetch frags(ks=1), MMA frags(ks=0) ----
        ldsmAB(buf, 1, af1, bf1);
#pragma unroll
        for (int mt = 0; mt < 4; mt++)
#pragma unroll
            for (int nt = 0; nt < 4; nt++)
                mma_bf16(acc[mt][nt], af0[mt], bf0[nt]);

        // ---- producer: issue stage s+3 (2 stages of empty slack) ----
        const int t = s + 3;
        if (t < nStages) {
            const int tb = t % NBUF;
            if (t >= NBUF)
                mbar_wait(EB + tb * 8, (uint32_t)(((t - NBUF) / NBUF) & 1));
            loadStage(t, tb);
        }
        // ---- consumer: fetch frags(s+1, ks=0) ----
        if (s + 1 < nStages) {
            const int nb = (s + 1) % NBUF;
            mbar_wait(FB + nb * 8, (uint32_t)(((s + 1) / NBUF) & 1));
            ldsmAB(nb, 0, af0, bf0);
        }
#pragma unroll
        for (int mt = 0; mt < 4; mt++)
#pragma unroll
            for (int nt = 0; nt < 4; nt++)
                mma_bf16(acc[mt][nt], af1[mt], bf1[nt]);

        if (lane == 0) mbar_arrive(EB + buf * 8);
    }
    __syncthreads();

    // ---- epilogue ----
    if (EPI == 2) {
        float* rsum = (float*)(smem_raw + 128);   // clear of mbarrier words
        if (tid < 128) rsum[tid] = 0.f;
        __syncthreads();
        __nv_bfloat16* Cb = (__nv_bfloat16*)Cg + sC * bz;
#pragma unroll
        for (int mt = 0; mt < 4; mt++) {
            int row = m0 + wm + mt * 16 + lr;
            float p0 = 0.f, p1 = 0.f;
#pragma unroll
            for (int nt = 0; nt < 4; nt++) {
                int col = n0 + wn + nt * 8 + 2 * lc;
                float e0 = __expf(acc[mt][nt][0] * scale);
                float e1 = __expf(acc[mt][nt][1] * scale);
                float e2 = __expf(acc[mt][nt][2] * scale);
                float e3 = __expf(acc[mt][nt][3] * scale);
                p0 += e0 + e1; p1 += e2 + e3;
                __nv_bfloat162 q0 = { __float2bfloat16(e0), __float2bfloat16(e1) };
                __nv_bfloat162 q1 = { __float2bfloat16(e2), __float2bfloat16(e3) };
                *(__nv_bfloat162*)&Cb[(size_t)row * ldC + col] = q0;
                *(__nv_bfloat162*)&Cb[(size_t)(row + 8) * ldC + col] = q1;
            }
            atomicAdd(&rsum[wm + mt * 16 + lr], p0);
            atomicAdd(&rsum[wm + mt * 16 + lr + 8], p1);
        }
        __syncthreads();
        if (tid < 128)
            atomicAdd(&rowsum[(size_t)bz * Ll + m0 + tid], rsum[tid]);
        return;
    }

#pragma unroll
    for (int mt = 0; mt < 4; mt++) {
#pragma unroll
        for (int nt = 0; nt < 4; nt++) {
            int row = m0 + wm + mt * 16 + lr;
            int col = n0 + wn + nt * 8 + 2 * lc;
            float v0 = acc[mt][nt][0], v1 = acc[mt][nt][1];
            float v2 = acc[mt][nt][2], v3 = acc[mt][nt][3];
            if (EPI == 1) {
                float b0 = bias[row], b1 = bias[row + 8];
                v0 += b0; v1 += b0; v2 += b1; v3 += b1;
                __nv_bfloat16* Cb = (__nv_bfloat16*)Cg + sC * bz;
                __nv_bfloat162 p0 = { __float2bfloat16(v0), __float2bfloat16(v1) };
                __nv_bfloat162 p1 = { __float2bfloat16(v2), __float2bfloat16(v3) };
                *(__nv_bfloat162*)&Cb[(size_t)row * ldC + col] = p0;
                *(__nv_bfloat162*)&Cb[(size_t)(row + 8) * ldC + col] = p1;
            } else if (EPI == 4) {
                const float* rs = rowsum + (size_t)bz * Ll;
                float2 rv = *(const float2*)&rs[col];
                float i0 = __fdividef(1.f, rv.x), i1 = __fdividef(1.f, rv.y);
                v0 *= i0; v1 *= i1; v2 *= i0; v3 *= i1;
                __nv_bfloat16* Cb = (__nv_bfloat16*)Cg + sC * bz;
                __nv_bfloat162 p0 = { __float2bfloat16(v0), __float2bfloat16(v1) };
                __nv_bfloat162 p1 = { __float2bfloat16(v2), __float2bfloat16(v3) };
                *(__nv_bfloat162*)&Cb[(size_t)row * ldC + col] = p0;
                *(__nv_bfloat162*)&Cb[(size_t)(row + 8) * ldC + col] = p1;
            } else { // EPI == 3
                float* Cf = (float*)Cg + sC * bz;
                float b0 = bias[row], b1 = bias[row + 8];
                const float* rp = resid + sC * bz;
                float2 r0 = *(const float2*)&rp[(size_t)row * ldC + col];
                float2 r1 = *(const float2*)&rp[(size_t)(row + 8) * ldC + col];
                v0 += b0 + r0.x; v1 += b0 + r0.y;
                v2 += b1 + r1.x; v3 += b1 + r1.y;
                *(float2*)&Cf[(size_t)row * ldC + col] = make_float2(v0, v1);
                *(float2*)&Cf[(size_t)(row + 8) * ldC + col] = make_float2(v2, v3);
            }
        }
    }
}

// ============================================================
extern "C" void kernel_launch(void* const* d_in, const int* in_sizes, int n_in,
                              void* d_out, int out_size)
{
    const float* x     = (const float*)d_in[0];
    const float* gamma = (const float*)d_in[1];
    const float* beta  = (const float*)d_in[2];
    const float* Wq    = (const float*)d_in[3];
    const float* bq    = (const float*)d_in[4];
    const float* Wk    = (const float*)d_in[5];
    const float* bk    = (const float*)d_in[6];
    const float* Wv    = (const float*)d_in[7];
    const float* bv    = (const float*)d_in[8];
    const float* Wp    = (const float*)d_in[9];
    const float* bp    = (const float*)d_in[10];
    float* out = (float*)d_out;

    __nv_bfloat16 *Wall, *Wpb, *xb, *qkv, *P, *h;
    float *ball, *rowsum;
    cudaGetSymbolAddress((void**)&Wall, g_Wall);
    cudaGetSymbolAddress((void**)&Wpb,  g_Wpb);
    cudaGetSymbolAddress((void**)&xb,   g_xb);
    cudaGetSymbolAddress((void**)&qkv,  g_qkv);
    cudaGetSymbolAddress((void**)&P,    g_P);
    cudaGetSymbolAddress((void**)&h,    g_h);
    cudaGetSymbolAddress((void**)&ball, g_ball);
    cudaGetSymbolAddress((void**)&rowsum, g_rowsum);

    const int SM_TF = 640 + NBUF * (128 * 80 + 32 * 272);   // 95360
    const int SM_FF = 640 + NBUF * (32 * 272 + 32 * 272);   // 87680
    const int SM_TT = 640 + NBUF * (128 * 80 + 128 * 80);   // 103040
    cudaFuncSetAttribute(gemm_bf<true,  false, 1>, cudaFuncAttributeMaxDynamicSharedMemorySize, SM_TF);
    cudaFuncSetAttribute(gemm_bf<false, false, 2>, cudaFuncAttributeMaxDynamicSharedMemorySize, SM_FF);
    cudaFuncSetAttribute(gemm_bf<true,  true,  4>, cudaFuncAttributeMaxDynamicSharedMemorySize, SM_TT);
    cudaFuncSetAttribute(gemm_bf<true,  false, 3>, cudaFuncAttributeMaxDynamicSharedMemorySize, SM_TF);

    bn_stats_kernel<<<Cc, 256>>>(x, gamma, beta);
    fold_kernel<<<C3 + 256, 256>>>(Wq, bq, Wk, bk, Wv, bv, Wp);
    cudaMemsetAsync(rowsum, 0, (size_t)Bb * Ll * sizeof(float), 0);

    // QKV: qkv[o][l] = sum_c Wall[o][c] xb[c][l] + ball[o]   -> bf16
    gemm_bf<true, false, 1><<<dim3(Ll / 128, C3 / 128, Bb), 256, SM_TF>>>(
        Wall, xb, qkv, Cc, Cc, Ll, Ll,
        0, (size_t)Cc * Ll, (size_t)C3 * Ll, ball, nullptr, nullptr, 0.f);

    // scores+exp: P[i][j] = exp(scale * sum_c q[c][i] k[c][j]), rowsum accum
    gemm_bf<false, false, 2><<<dim3(Ll / 128, Ll / 128, Bb), 256, SM_FF>>>(
        qkv, qkv + (size_t)Cc * Ll, P, Cc, Ll, Ll, Ll,
        (size_t)C3 * Ll, (size_t)C3 * Ll, (size_t)Ll * Ll,
        nullptr, nullptr, rowsum, rsqrtf((float)Cc));

    // AV + normalize: h[c][i] = (sum_j V[c][j] P[i][j]) / rowsum[i]  -> bf16
    gemm_bf<true, true, 4><<<dim3(Ll / 128, Cc / 128, Bb), 256, SM_TT>>>(
        qkv + (size_t)2 * Cc * Ll, P, h, Ll, Ll, Ll, Ll,
        (size_t)C3 * Ll, (size_t)Ll * Ll, (size_t)Cc * Ll,
        nullptr, nullptr, rowsum, 0.f);

    // proj: out[o][l] = x[o][l] + bp[o] + sum_c Wp[o][c] h[c][l]  -> fp32
    gemm_bf<true, false, 3><<<dim3(Ll / 128, Cc / 128, Bb), 256, SM_TF>>>(
        Wpb, h, out, Cc, Cc, Ll, Ll,
        0, (size_t)Cc * Ll, (size_t)Cc * Ll, bp, x, nullptr, 0.f);
}